// round 2
// baseline (speedup 1.0000x reference)
#include <cuda_runtime.h>

// Pairwise Jensen-Shannon divergence (in bits):
//   out[i,j] = sum_d [ 0.5*a*lg2(a) + 0.5*b*lg2(b) - m*lg2(m) ],  m = (a+b)/2
// Computed directly in log2 so the final /ln2 is free, and in per-element
// difference form so the accumulator stays small and well-conditioned.

static constexpr int Dc = 512;   // feature dim (fixed by problem)
static constexpr int TM = 64;    // output tile rows  per block
static constexpr int TN = 64;    // output tile cols  per block
static constexpr int KB = 32;    // K-chunk staged in smem
static constexpr int LDPAD = 66; // row stride (float2) -> 528B = 33*16, keeps
                                 // float4 alignment and breaks the d*64 bank pattern

__global__ __launch_bounds__(256, 2)
void jsd_kernel(const float* __restrict__ A, const float* __restrict__ B,
                float* __restrict__ out, int M) {
    // As[d][r] = (0.5*a, 0.5*a*log2(a)) for row (i0+r), feature (k0+d)
    __shared__ float2 As[KB][LDPAD];
    __shared__ float2 Bs[KB][LDPAD];

    const int tid = threadIdx.x;
    const int tx = tid & 15;       // 16 threads across N-tile cols
    const int ty = tid >> 4;       // 16 threads across M-tile rows
    const int i0 = blockIdx.y * TM;
    const int j0 = blockIdx.x * TN;

    float acc[4][4];
#pragma unroll
    for (int u = 0; u < 4; ++u)
#pragma unroll
        for (int v = 0; v < 4; ++v) acc[u][v] = 0.0f;

    for (int k0 = 0; k0 < Dc; k0 += KB) {
        // ---- stage A tile: 64 rows x 32 features, coalesced along d ----
#pragma unroll
        for (int e = 0; e < TM * KB; e += 256) {
            int idx = e + tid;
            int r = idx >> 5;        // row in tile   (KB==32)
            int d = idx & 31;        // feature in chunk
            float v  = A[(size_t)(i0 + r) * Dc + (k0 + d)];
            float lg = __log2f(v);
            float vh = 0.5f * v;
            As[d][r] = make_float2(vh, vh * lg);
        }
        // ---- stage B tile ----
#pragma unroll
        for (int e = 0; e < TN * KB; e += 256) {
            int idx = e + tid;
            int r = idx >> 5;
            int d = idx & 31;
            float v  = B[(size_t)(j0 + r) * Dc + (k0 + d)];
            float lg = __log2f(v);
            float vh = 0.5f * v;
            Bs[d][r] = make_float2(vh, vh * lg);
        }
        __syncthreads();

        // ---- inner: 16 midpoint logs per thread per d (MUFU-bound) ----
#pragma unroll 2
        for (int d = 0; d < KB; ++d) {
            float4 a01 = *reinterpret_cast<const float4*>(&As[d][ty * 4]);
            float4 a23 = *reinterpret_cast<const float4*>(&As[d][ty * 4 + 2]);
            float4 b01 = *reinterpret_cast<const float4*>(&Bs[d][tx * 4]);
            float4 b23 = *reinterpret_cast<const float4*>(&Bs[d][tx * 4 + 2]);
            float ax[4] = {a01.x, a01.z, a23.x, a23.z};
            float ay[4] = {a01.y, a01.w, a23.y, a23.w};
            float bx[4] = {b01.x, b01.z, b23.x, b23.z};
            float by[4] = {b01.y, b01.w, b23.y, b23.w};
#pragma unroll
            for (int u = 0; u < 4; ++u)
#pragma unroll
                for (int v = 0; v < 4; ++v) {
                    float m  = ax[u] + bx[v];           // midpoint (x2 scale folded: already halves)
                    float s  = ay[u] + by[v];           // 0.5 a lg a + 0.5 b lg b
                    float lg = __log2f(m);              // MUFU.LG2
                    acc[u][v] += __fmaf_rn(-m, lg, s);  // += s - m*lg2(m)  (>= 0)
                }
        }
        __syncthreads();
    }

    // ---- store 4x4 micro-tile as float4 rows (coalesced) ----
#pragma unroll
    for (int u = 0; u < 4; ++u) {
        float4 o = make_float4(acc[u][0], acc[u][1], acc[u][2], acc[u][3]);
        *reinterpret_cast<float4*>(
            &out[(size_t)(i0 + ty * 4 + u) * M + (j0 + tx * 4)]) = o;
    }
}

extern "C" void kernel_launch(void* const* d_in, const int* in_sizes, int n_in,
                              void* d_out, int out_size) {
    const float* A = (const float*)d_in[0];
    const float* B = (const float*)d_in[1];
    float* out = (float*)d_out;
    const int N = in_sizes[0] / Dc;   // 1024
    const int M = in_sizes[1] / Dc;   // 1024
    dim3 grid(M / TN, N / TM);        // 16 x 16 blocks
    jsd_kernel<<<grid, 256>>>(A, B, out, M);
}

// round 3
// speedup vs baseline: 1.3539x; 1.3539x over previous
#include <cuda_runtime.h>

// out[i,j] = sum_d [ -m*lg2(m) ] + hA[i] + hB[j],  m = 0.5*a + 0.5*b
// where hA[i] = sum_d 0.5*a*lg2(a)  (precomputed per row), same for hB.
// Working in log2 makes the final /ln2 free.

static constexpr int Dc = 512;   // feature dim (fixed)
static constexpr int TM = 32;    // tile rows
static constexpr int TN = 32;    // tile cols
static constexpr int KB = 32;    // K-chunk
static constexpr int LDA = 36;   // smem row pad (floats): mult of 4 for vec loads

__device__ float g_hA[1024];
__device__ float g_hB[1024];

// ---------------- row half-entropy precompute --------------------------
// One block per row (A rows then B rows). 128 threads x 1 float4 each = 512.
__global__ __launch_bounds__(128)
void row_entropy_kernel(const float* __restrict__ A, const float* __restrict__ B,
                        int nA) {
    const int row = blockIdx.x;
    const bool isA = row < nA;
    const int r = isA ? row : row - nA;
    const float* src = isA ? A : B;
    const int t = threadIdx.x;

    float4 v = reinterpret_cast<const float4*>(src + (size_t)r * Dc)[t];
    float s = 0.5f * v.x * __log2f(v.x)
            + 0.5f * v.y * __log2f(v.y)
            + 0.5f * v.z * __log2f(v.z)
            + 0.5f * v.w * __log2f(v.w);

    __shared__ float red[128];
    red[t] = s;
    __syncthreads();
    #pragma unroll
    for (int off = 64; off > 0; off >>= 1) {
        if (t < off) red[t] += red[t + off];
        __syncthreads();
    }
    if (t == 0) {
        if (isA) g_hA[r] = red[0]; else g_hB[r] = red[0];
    }
}

// ---------------- main pairwise kernel ----------------------------------
// 32x32 output tile, 128 threads, 2x4 micro-tile per thread. 8 blocks/SM.
__global__ __launch_bounds__(128, 8)
void jsd_main(const float* __restrict__ A, const float* __restrict__ B,
              float* __restrict__ out, int M) {
    __shared__ float As[KB][LDA];   // As[d][r] = 0.5 * a[i0+r][k0+d]
    __shared__ float Bs[KB][LDA];

    const int tid = threadIdx.x;
    const int tx = tid & 7;         // 8 col-groups of 4
    const int ty = tid >> 3;        // 16 row-groups of 2
    const int i0 = blockIdx.y * TM;
    const int j0 = blockIdx.x * TN;

    float acc[2][4] = {};

    for (int k0 = 0; k0 < Dc; k0 += KB) {
        // stage 32x32 tiles, coalesced along d (8 elems per thread per tile)
        #pragma unroll
        for (int e = 0; e < TM * KB; e += 128) {
            int idx = e + tid;
            int r = idx >> 5;       // KB == 32
            int d = idx & 31;
            As[d][r] = 0.5f * A[(size_t)(i0 + r) * Dc + (k0 + d)];
            Bs[d][r] = 0.5f * B[(size_t)(j0 + r) * Dc + (k0 + d)];
        }
        __syncthreads();

        #pragma unroll 8
        for (int d = 0; d < KB; ++d) {
            float2 a2 = *reinterpret_cast<const float2*>(&As[d][ty * 2]);
            float4 b4 = *reinterpret_cast<const float4*>(&Bs[d][tx * 4]);
            float av[2] = {a2.x, a2.y};
            float bv[4] = {b4.x, b4.y, b4.z, b4.w};
            #pragma unroll
            for (int u = 0; u < 2; ++u)
                #pragma unroll
                for (int v = 0; v < 4; ++v) {
                    float m = av[u] + bv[v];                      // FADD
                    acc[u][v] = __fmaf_rn(-m, __log2f(m), acc[u][v]); // MUFU + FFMA
                }
        }
        __syncthreads();
    }

    // epilogue: add per-row constants, store coalesced float4
    float4 hb = *reinterpret_cast<const float4*>(&g_hB[j0 + tx * 4]);
    #pragma unroll
    for (int u = 0; u < 2; ++u) {
        float ha = g_hA[i0 + ty * 2 + u];
        float4 o = make_float4(acc[u][0] + ha + hb.x,
                               acc[u][1] + ha + hb.y,
                               acc[u][2] + ha + hb.z,
                               acc[u][3] + ha + hb.w);
        *reinterpret_cast<float4*>(
            &out[(size_t)(i0 + ty * 2 + u) * M + (j0 + tx * 4)]) = o;
    }
}

extern "C" void kernel_launch(void* const* d_in, const int* in_sizes, int n_in,
                              void* d_out, int out_size) {
    const float* A = (const float*)d_in[0];
    const float* B = (const float*)d_in[1];
    float* out = (float*)d_out;
    const int N = in_sizes[0] / Dc;   // 1024
    const int M = in_sizes[1] / Dc;   // 1024

    row_entropy_kernel<<<N + M, 128>>>(A, B, N);

    dim3 grid(M / TN, N / TM);        // 32 x 32 = 1024 blocks
    jsd_main<<<grid, 128>>>(A, B, out, M);
}